// round 12
// baseline (speedup 1.0000x reference)
#include <cuda_runtime.h>

// Potts energy: out[b] = sum_{i<=j} W[i,j] * [(1-x_i)(1-x_j) + x_i*x_j]
// Per masked tile row i:  E_i(b) = (1-x_bi)*u_i + t_i(b)*(2*x_bi - 1)
//   t_i(b) = sum_j U_ij x_bj,  u_i = sum_j U_ij  (batch independent)
// R12: V transposed ONCE to Vt[n][b] (kernel 1); main kernel reads x via
// coalesced LDG into registers -> no V smem staging at all. W i-major in smem
// (coalesced stage, warp-uniform broadcast reads). 64x64 tiles split into
// four 16-row i-slices -> 544 CTAs, 512 thr, 2 CTAs/SM (32 warps/SM).

#define Bb      128
#define Nn      1024
#define T       64
#define HI      16
#define NT      16
#define NCTAS   544
#define WDS     68      // W slice row stride (floats), 16B-aligned rows
#define THREADS 512

__device__ float        g_Vt[Nn * Bb];   // V transposed [n][b]
__device__ float        g_accum[Bb];
__device__ unsigned int g_count;

// ---- kernel 1: V[128][1024] -> Vt[1024][128] ----
__global__ void transpose_k(const float* __restrict__ V) {
    __shared__ float ts[32][33];
    const int bx = blockIdx.x;           // n-tile (32)
    const int by = blockIdx.y;           // b-tile (4)
    const int tx = threadIdx.x;          // 0..31
    const int ty = threadIdx.y;          // 0..7
    #pragma unroll
    for (int k = 0; k < 32; k += 8)
        ts[ty + k][tx] = V[(size_t)(by * 32 + ty + k) * Nn + bx * 32 + tx];
    __syncthreads();
    #pragma unroll
    for (int k = 0; k < 32; k += 8)
        g_Vt[(size_t)(bx * 32 + ty + k) * Bb + by * 32 + tx] = ts[tx][ty + k];
}

// ---- kernel 2: main ----
__global__ void __launch_bounds__(THREADS, 2)
potts_k(const float* __restrict__ W,    // [1024,1024]
        float* __restrict__ out)        // [128]
{
    __shared__ float Wd[HI * WDS];       // masked W slice, i-major
    __shared__ float u[HI];              // row sums
    __shared__ float usp[HI * 8];        // partials
    __shared__ float red[THREADS];

    const int tid = threadIdx.x;
    const int b   = tid & 127;           // batch (lane-consecutive -> coalesced)
    const int jq  = tid >> 7;            // j-quarter 0..3 (warp-uniform)

    // ---- CTA -> (tile, i-slice) ----
    int k = blockIdx.x >> 2;
    const int sub = blockIdx.x & 3;
    int bi = 0;
    while (k >= NT - bi) { k -= NT - bi; bi++; }
    const int bj   = bi + k;
    const int gi0h = bi * T + sub * HI;
    const int gj0  = bj * T;
    const bool diag = (bi == bj);
    const int iofs = sub * HI;

    // ---- x straight from Vt into registers (coalesced LDG.32) ----
    float vj[16];
    #pragma unroll
    for (int jj = 0; jj < 16; jj++)
        vj[jj] = g_Vt[(size_t)(gj0 + jq * 16 + jj) * Bb + b];
    float vi[HI];
    #pragma unroll
    for (int i = 0; i < HI; i++)
        vi[i] = g_Vt[(size_t)(gi0h + i) * Bb + b];

    // ---- stage W slice i-major, masked (256 float4, coalesced) ----
    if (tid < 256) {
        int ii = tid >> 4;               // 0..15 local i
        int q  = tid & 15;
        float4 w = *(const float4*)(W + (size_t)(gi0h + ii) * Nn + gj0 + q * 4);
        int gr = iofs + ii, j0 = q * 4;
        if (diag) {
            if (gr > j0 + 0) w.x = 0.0f;
            if (gr > j0 + 1) w.y = 0.0f;
            if (gr > j0 + 2) w.z = 0.0f;
            if (gr > j0 + 3) w.w = 0.0f;
        }
        *(float4*)(Wd + ii * WDS + j0) = w;
    }
    __syncthreads();

    // ---- cooperative row sums u_i (contiguous reads) ----
    if (tid < 128) {
        int i2 = tid >> 3, c2 = tid & 7;
        float pr = 0.0f;
        #pragma unroll
        for (int t = 0; t < 8; t++) pr += Wd[i2 * WDS + c2 * 8 + t];
        usp[i2 * 8 + c2] = pr;
    }
    __syncthreads();
    if (tid < HI) {
        float s = 0.0f;
        #pragma unroll
        for (int c = 0; c < 8; c++) s += usp[tid * 8 + c];
        u[tid] = s;
    }
    __syncthreads();

    // ---- mainloop: serial i; W slice = warp-uniform broadcast LDS.128 ----
    float qacc = 0.0f;
    #pragma unroll 4
    for (int i = 0; i < HI; i++) {
        const float4* wr = (const float4*)(Wd + i * WDS + jq * 16);
        float t0 = 0.0f, t1 = 0.0f, t2 = 0.0f, t3 = 0.0f;
        #pragma unroll
        for (int kk = 0; kk < 4; kk++) {
            float4 w = wr[kk];
            t0 = fmaf(w.x, vj[4 * kk + 0], t0);
            t1 = fmaf(w.y, vj[4 * kk + 1], t1);
            t2 = fmaf(w.z, vj[4 * kk + 2], t2);
            t3 = fmaf(w.w, vj[4 * kk + 3], t3);
        }
        float t = (t0 + t1) + (t2 + t3);
        qacc = fmaf(t, 2.0f * vi[i] - 1.0f, qacc);
    }

    // ---- linear term once per i-slice (jq==0 warps; warp-uniform) ----
    if (jq == 0) {
        #pragma unroll
        for (int i = 0; i < HI; i++)
            qacc = fmaf(u[i], 1.0f - vi[i], qacc);
    }

    red[tid] = qacc;                     // tid = jq*128 + b (bijective)
    __syncthreads();

    // ---- per-batch reduction + global accumulate ----
    if (tid < Bb) {
        float e = red[tid] + red[tid + 128] + red[tid + 256] + red[tid + 384];
        atomicAdd(&g_accum[tid], e);
    }
    __threadfence();
    __syncthreads();

    __shared__ bool last;
    if (tid == 0) last = (atomicAdd(&g_count, 1u) == NCTAS - 1);
    __syncthreads();

    if (last) {
        __threadfence();
        if (tid < Bb) out[tid] = atomicExch(&g_accum[tid], 0.0f);
        if (tid == 0) atomicExch(&g_count, 0u);
    }
}

extern "C" void kernel_launch(void* const* d_in, const int* in_sizes, int n_in,
                              void* d_out, int out_size)
{
    const float* V = (const float*)d_in[0];   // vector [128,1024]
    const float* W = (const float*)d_in[1];   // interactions [1024,1024]
    float* out = (float*)d_out;               // [128] fp32

    dim3 tgrid(32, 4), tblk(32, 8);
    transpose_k<<<tgrid, tblk>>>(V);
    potts_k<<<NCTAS, THREADS>>>(W, out);
}

// round 13
// speedup vs baseline: 1.1214x; 1.1214x over previous
#include <cuda_runtime.h>

// Potts energy: out[b] = sum_{i<=j} W[i,j] * [(1-x_i)(1-x_j) + x_i*x_j]
// Per masked tile row i:  E_i(b) = u_i*(1-x_bi) + t_i(b)*(2*x_bi - 1)
//   t_i(b) = sum_j U_ij x_bj,  u_i = sum_j U_ij  (batch independent)
// R13: Vt[n][b] prepass (all V traffic coalesced). Main kernel: 136 CTAs
// (one full 64x64 upper-tri tile, ONE wave, 1 CTA/SM) x 512 threads.
// vm = 2x-1 staged by coalesced copy; vj in regs from Vt; W i-major smem,
// warp-uniform broadcast reads. Scalar FFMA only.

#define Bb      128
#define Nn      1024
#define T       64
#define NT      16
#define NCTAS   136
#define WDS     68      // Wd row stride (floats), 16B-aligned rows
#define VMS     132     // Vm row stride (mult of 4 -> float4 stores OK)
#define THREADS 512

__device__ float        g_Vt[Nn * Bb];   // V transposed [n][b]
__device__ float        g_accum[Bb];
__device__ unsigned int g_count;

// ---- kernel 1: V[128][1024] -> Vt[1024][128] ----
__global__ void transpose_k(const float* __restrict__ V) {
    __shared__ float ts[32][33];
    const int bx = blockIdx.x;           // n-tile (32)
    const int by = blockIdx.y;           // b-tile (4)
    const int tx = threadIdx.x;          // 0..31
    const int ty = threadIdx.y;          // 0..7
    #pragma unroll
    for (int k = 0; k < 32; k += 8)
        ts[ty + k][tx] = V[(size_t)(by * 32 + ty + k) * Nn + bx * 32 + tx];
    __syncthreads();
    #pragma unroll
    for (int k = 0; k < 32; k += 8)
        g_Vt[(size_t)(bx * 32 + ty + k) * Bb + by * 32 + tx] = ts[tx][ty + k];
}

extern __shared__ float smf[];

// ---- kernel 2: main ----
__global__ void __launch_bounds__(THREADS, 1)
potts_k(const float* __restrict__ W,    // [1024,1024]
        float* __restrict__ out)        // [128]
{
    float* Wd  = smf;                    // [64][WDS] masked tile, i-major
    float* Vm  = Wd + T * WDS;           // [64][VMS] vm = 2x-1, [i][b]
    float* uh  = Vm + T * VMS;           // [64] u/2
    float* usp = uh + T;                 // [64][8] partials
    float* red = usp + 512;              // [512]

    const int tid = threadIdx.x;
    const int b   = tid & 127;           // batch (lane-consecutive)
    const int jq  = tid >> 7;            // j-quarter (warp-uniform)

    // ---- tile (bi,bj) from linear upper-tri index ----
    int k = blockIdx.x;
    int bi = 0;
    while (k >= NT - bi) { k -= NT - bi; bi++; }
    const int bj  = bi + k;
    const int gi0 = bi * T;
    const int gj0 = bj * T;
    const bool diag = (bi == bj);

    // ---- vj regs straight from Vt (coalesced LDG.32, overlaps W staging) ----
    float vj[16];
    #pragma unroll
    for (int jj = 0; jj < 16; jj++)
        vj[jj] = g_Vt[(size_t)(gj0 + jq * 16 + jj) * Bb + b];

    // ---- stage W tile i-major, masked (1024 float4, coalesced) ----
    #pragma unroll
    for (int it = 0; it < 2; it++) {
        int idx = it * THREADS + tid;
        int ii  = idx >> 4;              // 0..63
        int q   = idx & 15;
        float4 w = *(const float4*)(W + (size_t)(gi0 + ii) * Nn + gj0 + q * 4);
        int j0 = q * 4;
        if (diag) {
            if (ii > j0 + 0) w.x = 0.0f;
            if (ii > j0 + 1) w.y = 0.0f;
            if (ii > j0 + 2) w.z = 0.0f;
            if (ii > j0 + 3) w.w = 0.0f;
        }
        *(float4*)(Wd + ii * WDS + j0) = w;
    }

    // ---- stage Vm = 2x-1 by coalesced copy of Vt rows (2048 float4) ----
    #pragma unroll
    for (int it = 0; it < 4; it++) {
        int idx = it * THREADS + tid;
        int ii  = idx >> 5;              // 0..63
        int q   = idx & 31;              // float4 within 128 b
        float4 a = *(const float4*)(g_Vt + (size_t)(gi0 + ii) * Bb + q * 4);
        a.x = 2.0f * a.x - 1.0f;
        a.y = 2.0f * a.y - 1.0f;
        a.z = 2.0f * a.z - 1.0f;
        a.w = 2.0f * a.w - 1.0f;
        *(float4*)(Vm + ii * VMS + q * 4) = a;
    }
    __syncthreads();

    // ---- cooperative row sums u_i/2 (contiguous reads, 512 threads) ----
    {
        int i2 = tid >> 3, c2 = tid & 7;
        float pr = 0.0f;
        #pragma unroll
        for (int t = 0; t < 8; t++) pr += Wd[i2 * WDS + c2 * 8 + t];
        usp[i2 * 8 + c2] = pr;
    }
    __syncthreads();
    if (tid < T) {
        float s = 0.0f;
        #pragma unroll
        for (int c = 0; c < 8; c++) s += usp[tid * 8 + c];
        uh[tid] = 0.5f * s;              // u_i / 2
    }
    __syncthreads();

    // ---- mainloop: serial i; W slice = warp-uniform broadcast LDS.128 ----
    float qacc = 0.0f;
    #pragma unroll 4
    for (int i = 0; i < T; i++) {
        const float4* wr = (const float4*)(Wd + i * WDS + jq * 16);
        float t0 = 0.0f, t1 = 0.0f, t2 = 0.0f, t3 = 0.0f;
        #pragma unroll
        for (int kk = 0; kk < 4; kk++) {
            float4 w = wr[kk];
            t0 = fmaf(w.x, vj[4 * kk + 0], t0);
            t1 = fmaf(w.y, vj[4 * kk + 1], t1);
            t2 = fmaf(w.z, vj[4 * kk + 2], t2);
            t3 = fmaf(w.w, vj[4 * kk + 3], t3);
        }
        float t  = (t0 + t1) + (t2 + t3);
        float vm = Vm[i * VMS + b];      // conflict-free LDS.32
        qacc = fmaf(t, vm, qacc);        // quadratic: t_i * (2x_i - 1)
    }

    // ---- linear term on jq==0 warps: sum uh_i * (1 - vm_i) ----
    if (jq == 0) {
        float qc = 0.0f, ql = 0.0f;
        #pragma unroll 8
        for (int i = 0; i < T; i++) {
            float u  = uh[i];            // broadcast
            float vm = Vm[i * VMS + b];  // conflict-free
            qc += u;
            ql = fmaf(u, vm, ql);
        }
        qacc += qc - ql;
    }

    red[tid] = qacc;                     // bijective (jq,b)
    __syncthreads();

    // ---- per-batch reduction + global accumulate ----
    if (tid < Bb) {
        float e = red[tid] + red[tid + 128] + red[tid + 256] + red[tid + 384];
        atomicAdd(&g_accum[tid], e);
    }
    __threadfence();
    __syncthreads();

    __shared__ bool last;
    if (tid == 0) last = (atomicAdd(&g_count, 1u) == NCTAS - 1);
    __syncthreads();

    if (last) {
        __threadfence();
        if (tid < Bb) out[tid] = atomicExch(&g_accum[tid], 0.0f);
        if (tid == 0) atomicExch(&g_count, 0u);
    }
}

extern "C" void kernel_launch(void* const* d_in, const int* in_sizes, int n_in,
                              void* d_out, int out_size)
{
    const float* V = (const float*)d_in[0];   // vector [128,1024]
    const float* W = (const float*)d_in[1];   // interactions [1024,1024]
    float* out = (float*)d_out;               // [128] fp32

    const int smem_bytes = (T * WDS + T * VMS + T + 512 + 512)
                         * (int)sizeof(float);   // ~56.6 KB
    cudaFuncSetAttribute(potts_k, cudaFuncAttributeMaxDynamicSharedMemorySize,
                         smem_bytes);

    dim3 tgrid(32, 4), tblk(32, 8);
    transpose_k<<<tgrid, tblk>>>(V);
    potts_k<<<NCTAS, THREADS, smem_bytes>>>(W, out);
}